// round 7
// baseline (speedup 1.0000x reference)
#include <cuda_runtime.h>
#include <cuda_bf16.h>
#include <cstdint>

// FPQuantizer: per-row absmax clip is the identity, so the reference reduces
// to a pure elementwise flex-fp8 quantizer:
//   bias = 7.15625 (exact bf16)
//   L    = max(floor(log2|x| + bias), 1)
//   s    = 2^(L-12) * 2^(-0.15625)
//   out  = rint(x / s) * s
// Transcendental-free via exponent-field bit tricks:
//   floor(log2|x| + 7.15625) = e + 7 + (mant >= 2^0.84375)
//
// R7: R6 structure (block-strided lane-contiguous MLP=4, 512 thr, 32 regs),
// but stores use DEFAULT (.wb) policy instead of .cs. Theory: evict-first
// stores force premature fragmented L2 writebacks that interleave badly with
// the read stream at the DRAM controller; .wb lets L2 batch full-line
// writebacks into longer same-direction bursts. Loads stay .cs (evict-first)
// so the dead read lines don't compete for L2 capacity.
// Ceiling context: R1-R6 all pin at 6.2-6.3 TB/s across occ 51-83%, MLP 1-8,
// persistent vs one-shot => chip-level mixed-R/W memory ceiling; traffic
// (256MB R + 256MB W fp32) is irreducible. This is the last untested knob.

#define QT_THRESH 1.79470907f   // 2^0.84375, fp32-rounded
#define QT_C      0.89735454f   // 2^(-0.15625)
#define QT_CINV   1.11438674f   // 2^(+0.15625)

__device__ __forceinline__ float fpq_quantize(float x) {
    uint32_t b = __float_as_uint(x) & 0x7fffffffu;
    int e = (int)(b >> 23) - 127;
    float mant = __uint_as_float((b & 0x7fffffu) | 0x3f800000u);
    int L = e + 7 + (mant >= QT_THRESH ? 1 : 0);
    L = (L < 1) ? 1 : L;                       // x==0 -> L clamped to 1 -> out 0. Matches ref.
    int k = L - 12;
    float p    = __uint_as_float((uint32_t)(k + 127) << 23);
    float pinv = __uint_as_float((uint32_t)(127 - k) << 23);
    return rintf(x * (pinv * QT_CINV)) * (p * QT_C);  // round-half-even == jnp.round
}

__device__ __forceinline__ float4 fpq_quantize4(float4 v) {
    float4 q;
    q.x = fpq_quantize(v.x);
    q.y = fpq_quantize(v.y);
    q.z = fpq_quantize(v.z);
    q.w = fpq_quantize(v.w);
    return q;
}

#define THREADS 512
#define VPT 4   // float4 vectors per thread

// Block processes VPT*THREADS float4s; thread t handles t + k*THREADS within
// the block tile — every memory instruction is warp-contiguous (512B/warp).
__global__ __launch_bounds__(THREADS) void FPQuantizer_76312978915927_kernel(
    const float4* __restrict__ x, float4* __restrict__ out, int n4)
{
    const int T = THREADS;
    int base = blockIdx.x * (T * VPT) + threadIdx.x;

    if (base + (VPT - 1) * T < n4) {
        // front-batch 4 independent, fully-coalesced loads (MLP=4, evict-first)
        float4 v0 = __ldcs(x + base + 0 * T);
        float4 v1 = __ldcs(x + base + 1 * T);
        float4 v2 = __ldcs(x + base + 2 * T);
        float4 v3 = __ldcs(x + base + 3 * T);
        // stores: default write-back policy -> L2 batches full-line writebacks
        out[base + 0 * T] = fpq_quantize4(v0);
        out[base + 1 * T] = fpq_quantize4(v1);
        out[base + 2 * T] = fpq_quantize4(v2);
        out[base + 3 * T] = fpq_quantize4(v3);
    } else {
        // ragged tail block (not hit for 8192x8192: 16M float4s / 2048 exact)
        #pragma unroll
        for (int k = 0; k < VPT; ++k) {
            int i = base + k * T;
            if (i < n4) out[i] = fpq_quantize4(__ldcs(x + i));
        }
    }
}

// Scalar tail kernel (defensive; n divisible by 4 here so it won't launch)
__global__ void FPQuantizer_tail_kernel(const float* __restrict__ x,
                                        float* __restrict__ out,
                                        int start, int n)
{
    int i = start + blockIdx.x * blockDim.x + threadIdx.x;
    if (i < n) out[i] = fpq_quantize(x[i]);
}

extern "C" void kernel_launch(void* const* d_in, const int* in_sizes, int n_in,
                              void* d_out, int out_size)
{
    const float* x = (const float*)d_in[0];
    float* out = (float*)d_out;

    int n = out_size;
    int n4 = n >> 2;                        // number of float4 elements
    const int per_block = THREADS * VPT;    // float4s per block

    if (n4 > 0) {
        int blocks = (n4 + per_block - 1) / per_block;
        FPQuantizer_76312978915927_kernel<<<blocks, THREADS>>>(
            (const float4*)x, (float4*)out, n4);
    }
    int tail_start = n4 << 2;
    int tail = n - tail_start;
    if (tail > 0) {
        FPQuantizer_tail_kernel<<<1, 128>>>(x, out, tail_start, n);
    }
}

// round 8
// speedup vs baseline: 1.0156x; 1.0156x over previous
#include <cuda_runtime.h>
#include <cuda_bf16.h>
#include <cstdint>

// FPQuantizer — FINAL (R8 = R6 locked in).
//
// Algebra: the reference's per-row absmax clip is the identity (clip(x, -max|row|,
// +max|row|) == x), so the whole op is a pure elementwise flex-fp8 quantizer:
//   bias = bf16(2^4 - log2(448) + log2(2 - 2^-4) - 1) = 7.15625 (exact in bf16)
//   L    = max(floor(log2|x| + bias), 1)
//   s    = 2^(L-12) * 2^(-0.15625)
//   out  = rint(x / s) * s            (rint == round-half-even == jnp.round)
// Transcendental-free: floor(log2|x| + 7.15625) = e + 7 + (mant >= 2^0.84375),
// scales built via exponent-field construction (exact pow2) * fp32 constants.
//
// Perf characterization (R1-R7): all coalesced MLP>=4 variants pin at
// 6.2-6.3 TB/s regardless of occupancy (51-83%), MLP (4-8), persistence, block
// size, or store cache policy => chip-level mixed-50/50-R/W memory ceiling
// (path-independent ~6300 B/cyc LTS/DRAM cap). Traffic is irreducible
// (256 MB fp32 read + 256 MB fp32 write, no reuse). Kernel is at its roofline
// (~76.5 us kernel time = 512 MB / 6.3 TB/s). Compute pipes all <= 33%.
//
// Config: block-strided lane-contiguous addressing (every LDG.128/STG.128 is
// warp-contiguous 512B), 4 front-batched loads per thread (MLP=4), 512
// threads/block, .cs streaming hints both directions, 32 regs, occ ~76%.

#define QT_THRESH 1.79470907f   // 2^0.84375, fp32-rounded
#define QT_C      0.89735454f   // 2^(-0.15625)
#define QT_CINV   1.11438674f   // 2^(+0.15625)

__device__ __forceinline__ float fpq_quantize(float x) {
    uint32_t b = __float_as_uint(x) & 0x7fffffffu;
    int e = (int)(b >> 23) - 127;
    float mant = __uint_as_float((b & 0x7fffffu) | 0x3f800000u);
    int L = e + 7 + (mant >= QT_THRESH ? 1 : 0);
    L = (L < 1) ? 1 : L;                       // x==0 -> L clamped to 1 -> out 0. Matches ref.
    int k = L - 12;
    float p    = __uint_as_float((uint32_t)(k + 127) << 23);
    float pinv = __uint_as_float((uint32_t)(127 - k) << 23);
    return rintf(x * (pinv * QT_CINV)) * (p * QT_C);
}

__device__ __forceinline__ float4 fpq_quantize4(float4 v) {
    float4 q;
    q.x = fpq_quantize(v.x);
    q.y = fpq_quantize(v.y);
    q.z = fpq_quantize(v.z);
    q.w = fpq_quantize(v.w);
    return q;
}

#define THREADS 512
#define VPT 4   // float4 vectors per thread

// Block processes VPT*THREADS float4s; thread t handles t + k*THREADS within
// the block tile — every memory instruction is warp-contiguous (512B/warp).
__global__ __launch_bounds__(THREADS) void FPQuantizer_76312978915927_kernel(
    const float4* __restrict__ x, float4* __restrict__ out, int n4)
{
    const int T = THREADS;
    int base = blockIdx.x * (T * VPT) + threadIdx.x;

    if (base + (VPT - 1) * T < n4) {
        // front-batch 4 independent, fully-coalesced loads (MLP=4, evict-first)
        float4 v0 = __ldcs(x + base + 0 * T);
        float4 v1 = __ldcs(x + base + 1 * T);
        float4 v2 = __ldcs(x + base + 2 * T);
        float4 v3 = __ldcs(x + base + 3 * T);
        __stcs(out + base + 0 * T, fpq_quantize4(v0));
        __stcs(out + base + 1 * T, fpq_quantize4(v1));
        __stcs(out + base + 2 * T, fpq_quantize4(v2));
        __stcs(out + base + 3 * T, fpq_quantize4(v3));
    } else {
        // ragged tail block (not hit for 8192x8192: 16M float4s / 2048 exact)
        #pragma unroll
        for (int k = 0; k < VPT; ++k) {
            int i = base + k * T;
            if (i < n4) __stcs(out + i, fpq_quantize4(__ldcs(x + i)));
        }
    }
}

// Scalar tail kernel (defensive; n divisible by 4 here so it won't launch)
__global__ void FPQuantizer_tail_kernel(const float* __restrict__ x,
                                        float* __restrict__ out,
                                        int start, int n)
{
    int i = start + blockIdx.x * blockDim.x + threadIdx.x;
    if (i < n) out[i] = fpq_quantize(x[i]);
}

extern "C" void kernel_launch(void* const* d_in, const int* in_sizes, int n_in,
                              void* d_out, int out_size)
{
    const float* x = (const float*)d_in[0];
    float* out = (float*)d_out;

    int n = out_size;
    int n4 = n >> 2;                        // number of float4 elements
    const int per_block = THREADS * VPT;    // float4s per block

    if (n4 > 0) {
        int blocks = (n4 + per_block - 1) / per_block;
        FPQuantizer_76312978915927_kernel<<<blocks, THREADS>>>(
            (const float4*)x, (float4*)out, n4);
    }
    int tail_start = n4 << 2;
    int tail = n - tail_start;
    if (tail > 0) {
        FPQuantizer_tail_kernel<<<1, 128>>>(x, out, tail_start, n);
    }
}

// round 9
// speedup vs baseline: 1.0180x; 1.0023x over previous
#include <cuda_runtime.h>
#include <cuda_bf16.h>
#include <cstdint>

// FPQuantizer: per-row absmax clip is the identity, so the reference reduces
// to a pure elementwise flex-fp8 quantizer:
//   bias = 7.15625 (exact bf16)
//   L    = max(floor(log2|x| + bias), 1)
//   s    = 2^(L-12) * 2^(-0.15625)
//   out  = rint(x / s) * s            (rint == round-half-even == jnp.round)
// Transcendental-free via exponent bit tricks:
//   floor(log2|x| + 7.15625) = e + 7 + (mant >= 2^0.84375)
//
// R9: WARP-CONTIGUOUS tiling. Previous block-strided layout gave each warp
// four 512B runs spaced 8KB apart; here each warp owns one contiguous 2KB
// run (4 consecutive warp-wide LDG.128 wavefronts) -> longer same-row DRAM
// bursts per channel. Everything else identical to the best config (MLP=4
// front-batched, 512 thr, .cs both ways, 32 regs).

#define QT_THRESH 1.79470907f   // 2^0.84375, fp32-rounded
#define QT_C      0.89735454f   // 2^(-0.15625)
#define QT_CINV   1.11438674f   // 2^(+0.15625)

__device__ __forceinline__ float fpq_quantize(float x) {
    uint32_t b = __float_as_uint(x) & 0x7fffffffu;
    int e = (int)(b >> 23) - 127;
    float mant = __uint_as_float((b & 0x7fffffu) | 0x3f800000u);
    int L = e + 7 + (mant >= QT_THRESH ? 1 : 0);
    L = (L < 1) ? 1 : L;                       // x==0 -> L clamped to 1 -> out 0. Matches ref.
    int k = L - 12;
    float p    = __uint_as_float((uint32_t)(k + 127) << 23);
    float pinv = __uint_as_float((uint32_t)(127 - k) << 23);
    return rintf(x * (pinv * QT_CINV)) * (p * QT_C);
}

__device__ __forceinline__ float4 fpq_quantize4(float4 v) {
    float4 q;
    q.x = fpq_quantize(v.x);
    q.y = fpq_quantize(v.y);
    q.z = fpq_quantize(v.z);
    q.w = fpq_quantize(v.w);
    return q;
}

#define THREADS 512
#define VPT 4   // float4 vectors per thread

// Each warp owns a contiguous run of 32*VPT float4s (2KB); its 4 loads are
// consecutive 512B lines. Block tile = THREADS*VPT float4s, warps laid out
// contiguously within it.
__global__ __launch_bounds__(THREADS) void FPQuantizer_76312978915927_kernel(
    const float4* __restrict__ x, float4* __restrict__ out, int n4)
{
    int warp = threadIdx.x >> 5;
    int lane = threadIdx.x & 31;
    int base = blockIdx.x * (THREADS * VPT) + warp * (32 * VPT) + lane;

    if (base + (VPT - 1) * 32 < n4) {
        // front-batch 4 independent loads; warp covers 4 consecutive 512B lines
        float4 v0 = __ldcs(x + base + 0 * 32);
        float4 v1 = __ldcs(x + base + 1 * 32);
        float4 v2 = __ldcs(x + base + 2 * 32);
        float4 v3 = __ldcs(x + base + 3 * 32);
        __stcs(out + base + 0 * 32, fpq_quantize4(v0));
        __stcs(out + base + 1 * 32, fpq_quantize4(v1));
        __stcs(out + base + 2 * 32, fpq_quantize4(v2));
        __stcs(out + base + 3 * 32, fpq_quantize4(v3));
    } else {
        // ragged tail block (not hit for 8192x8192: 16M float4s / 2048 exact)
        #pragma unroll
        for (int k = 0; k < VPT; ++k) {
            int i = base + k * 32;
            if (i < n4) __stcs(out + i, fpq_quantize4(__ldcs(x + i)));
        }
    }
}

// Scalar tail kernel (defensive; n divisible by 4 here so it won't launch)
__global__ void FPQuantizer_tail_kernel(const float* __restrict__ x,
                                        float* __restrict__ out,
                                        int start, int n)
{
    int i = start + blockIdx.x * blockDim.x + threadIdx.x;
    if (i < n) out[i] = fpq_quantize(x[i]);
}

extern "C" void kernel_launch(void* const* d_in, const int* in_sizes, int n_in,
                              void* d_out, int out_size)
{
    const float* x = (const float*)d_in[0];
    float* out = (float*)d_out;

    int n = out_size;
    int n4 = n >> 2;                        // number of float4 elements
    const int per_block = THREADS * VPT;    // float4s per block

    if (n4 > 0) {
        int blocks = (n4 + per_block - 1) / per_block;
        FPQuantizer_76312978915927_kernel<<<blocks, THREADS>>>(
            (const float4*)x, (float4*)out, n4);
    }
    int tail_start = n4 << 2;
    int tail = n - tail_start;
    if (tail > 0) {
        FPQuantizer_tail_kernel<<<1, 128>>>(x, out, tail_start, n);
    }
}